// round 11
// baseline (speedup 1.0000x reference)
#include <cuda_runtime.h>
#include <cstdint>

#define LAYERS 8
#define EPS_F 1e-7f

// ---------------------------------------------------------------------------
// Quadratic-form kernel: p_j(x) = (1,u0,v0) C^j (1,u1,v1)^T,
// u0=cos x, v0=sin x, u1=cos(pi x/2), v1=sin(pi x/2).
// C^j built cooperatively per block; rows padded to 12 floats (3 x LDS.128).
// 8 elems/thread as TWO independent 4-elem groups (ILP), 512 blocks.
// out layout: [pi (B,3) | mu (B,3) | sigma (B,3)], row-major.
// ---------------------------------------------------------------------------

__device__ __forceinline__ void process_group(
    float4 xv, int t, const float4 (*sC4)[4][3],
    float* __restrict__ out, size_t regionStride)
{
    const float CLIP_LO = EPS_F;
    const float CLIP_HI = 1.0f - EPS_F;
    const float LN2 = 0.69314718056f;

    float xs[4] = {xv.x, xv.y, xv.z, xv.w};
    float u0[4], v0[4], u1[4], v1[4];
#pragma unroll
    for (int e = 0; e < 4; e++) {
        __sincosf(xs[e], &v0[e], &u0[e]);
        __sincosf(1.5707963267948966f * xs[e], &v1[e], &u1[e]);
    }

#pragma unroll
    for (int q = 0; q < 3; q++) {
        int nrows = (q == 0) ? 3 : 4;
        float p[4][4];   // [row][elem]
#pragma unroll
        for (int j = 0; j < 4; j++) {
            if (j >= nrows) break;
            float4 c0 = sC4[q][j][0];   // C0 C1 C2 C3
            float4 c1 = sC4[q][j][1];   // C4 C5 C6 C7
            float4 c2 = sC4[q][j][2];   // C8 - - -
#pragma unroll
            for (int e = 0; e < 4; e++) {
                float w0 = fmaf(v1[e], c0.z, fmaf(u1[e], c0.y, c0.x));
                float w1 = fmaf(v1[e], c1.y, fmaf(u1[e], c1.x, c0.w));
                float w2 = fmaf(v1[e], c2.x, fmaf(u1[e], c1.w, c1.z));
                p[j][e] = fmaf(v0[e], w2, fmaf(u0[e], w1, w0));
            }
        }

        float o[12];
#pragma unroll
        for (int e = 0; e < 4; e++) {
            if (q == 0) {
                float inv = __fdividef(1.0f, p[0][e] + p[1][e] + p[2][e]);
                o[e * 3 + 0] = p[0][e] * inv;
                o[e * 3 + 1] = p[1][e] * inv;
                o[e * 3 + 2] = p[2][e] * inv;
            } else {
                float pc[4];
#pragma unroll
                for (int j = 0; j < 4; j++)
                    pc[j] = fminf(fmaxf(p[j][e], CLIP_LO), CLIP_HI);
                if (q == 1) {
                    float l3 = __log2f(pc[3]);
                    o[e * 3 + 0] = (__log2f(pc[0]) - l3) * LN2;
                    o[e * 3 + 1] = (__log2f(pc[1]) - l3) * LN2;
                    o[e * 3 + 2] = (__log2f(pc[2]) - l3) * LN2;
                } else {
                    float inv = __fdividef(1.0f, pc[3]);
                    o[e * 3 + 0] = pc[0] * inv;
                    o[e * 3 + 1] = pc[1] * inv;
                    o[e * 3 + 2] = pc[2] * inv;
                }
            }
        }
        float4* dst = (float4*)(out + q * regionStride + (size_t)t * 12);
        dst[0] = make_float4(o[0], o[1], o[2],  o[3]);
        dst[1] = make_float4(o[4], o[5], o[6],  o[7]);
        dst[2] = make_float4(o[8], o[9], o[10], o[11]);
    }
}

__global__ void __launch_bounds__(256, 3)
qmdn_fused(const float4* __restrict__ x4,
           const float* __restrict__ wp,
           const float* __restrict__ wm,
           const float* __restrict__ ws,
           float* __restrict__ out, int B) {
    __shared__ float sR[3][LAYERS][2][2][2][2];
    __shared__ float sP[3][LAYERS][4][4][2];
    __shared__ float sM[3][4][4][2];
    __shared__ float4 sC4[3][4][3];

    int tid  = threadIdx.x;
    int wid  = tid >> 5;
    int lane = tid & 31;

    // issue both group loads immediately (overlap with prologue + barrier)
    int nGroups = B >> 2;
    int stride  = gridDim.x * blockDim.x;
    int t0 = blockIdx.x * blockDim.x + tid;
    int t1 = t0 + stride;
    float4 xa = (t0 < nGroups) ? x4[t0] : make_float4(0.f, 0.f, 0.f, 0.f);
    float4 xb = (t1 < nGroups) ? x4[t1] : make_float4(0.f, 0.f, 0.f, 0.f);

    if (wid < 3) {
        int q = wid;
        const float* w = (q == 0) ? wp : (q == 1) ? wm : ws;

        if (lane < 16) {   // 16 Rot gates in parallel
            int l = lane >> 1, wi = lane & 1;
            float phi = w[(l * 2 + wi) * 3 + 0];
            float th  = w[(l * 2 + wi) * 3 + 1];
            float om  = w[(l * 2 + wi) * 3 + 2];
            float st, ct, sapo, capo, samo, camo;
            __sincosf(0.5f * th, &st, &ct);
            __sincosf(0.5f * (phi + om), &sapo, &capo);
            __sincosf(0.5f * (phi - om), &samo, &camo);
            sR[q][l][wi][0][0][0] =  capo * ct;  sR[q][l][wi][0][0][1] = -sapo * ct;
            sR[q][l][wi][0][1][0] = -camo * st;  sR[q][l][wi][0][1][1] = -samo * st;
            sR[q][l][wi][1][0][0] =  camo * st;  sR[q][l][wi][1][0][1] = -samo * st;
            sR[q][l][wi][1][1][0] =  capo * ct;  sR[q][l][wi][1][1][1] =  sapo * ct;
        }
        __syncwarp();

        if (lane < 16) {   // per-layer permuted Kronecker
            int r = lane >> 2, c = lane & 3;
            const int src[4] = {0, 2, 3, 1};
            int rs = src[r], i0 = rs >> 1, j0 = rs & 1, i1 = c >> 1, j1 = c & 1;
#pragma unroll
            for (int l = 0; l < LAYERS; l++) {
                float ar = sR[q][l][0][i0][i1][0], ai = sR[q][l][0][i0][i1][1];
                float br = sR[q][l][1][j0][j1][0], bi = sR[q][l][1][j0][j1][1];
                sP[q][l][r][c][0] = ar * br - ai * bi;
                sP[q][l][r][c][1] = ar * bi + ai * br;
            }
        }
        __syncwarp();

        for (int np = 4; np >= 1; np >>= 1) {   // log-tree product
            float res[4][2];
            if (lane < 16) {
                int r = lane >> 2, c = lane & 3;
                for (int m = 0; m < np; m++) {
                    float sr = 0.f, si = 0.f;
#pragma unroll
                    for (int k = 0; k < 4; k++) {
                        float ar = sP[q][2 * m + 1][r][k][0], ai = sP[q][2 * m + 1][r][k][1];
                        float br = sP[q][2 * m][k][c][0],     bi = sP[q][2 * m][k][c][1];
                        sr += ar * br - ai * bi;
                        si += ar * bi + ai * br;
                    }
                    res[m][0] = sr; res[m][1] = si;
                }
            }
            __syncwarp();
            if (lane < 16) {
                int r = lane >> 2, c = lane & 3;
                for (int m = 0; m < np; m++) {
                    sP[q][m][r][c][0] = res[m][0];
                    sP[q][m][r][c][1] = res[m][1];
                }
            }
            __syncwarp();
        }

        if (lane < 16) {   // fold column phases {1,-i,-i,-1}
            int r = lane >> 2, c = lane & 3;
            float ur = sP[q][0][r][c][0], ui = sP[q][0][r][c][1];
            float mr, mi;
            if (c == 0)      { mr =  ur; mi =  ui; }
            else if (c == 3) { mr = -ur; mi = -ui; }
            else             { mr =  ui; mi = -ur; }
            sM[q][r][c][0] = mr;
            sM[q][r][c][1] = mi;
        }
        __syncwarp();

        if (lane < 4) {    // build padded C^j
            int j = lane;
            float mr[4], mi[4];
#pragma unroll
            for (int k = 0; k < 4; k++) { mr[k] = sM[q][j][k][0]; mi[k] = sM[q][j][k][1]; }
            const float bas[3][3] = { {0.5f,  0.5f, 0.f},
                                      {0.f,   0.f,  0.5f},
                                      {0.5f, -0.5f, 0.f} };
            float C[9] = {0,0,0,0,0,0,0,0,0};
#pragma unroll
            for (int k = 0; k < 4; k++)
#pragma unroll
                for (int l = 0; l < 4; l++) {
                    float Q = mr[k] * mr[l] + mi[k] * mi[l];
                    int a0 = (k >> 1) + (l >> 1);
                    int b1 = (k & 1) + (l & 1);
#pragma unroll
                    for (int al = 0; al < 3; al++)
#pragma unroll
                        for (int be = 0; be < 3; be++)
                            C[al * 3 + be] += Q * bas[a0][al] * bas[b1][be];
                }
            sC4[q][j][0] = make_float4(C[0], C[1], C[2], C[3]);
            sC4[q][j][1] = make_float4(C[4], C[5], C[6], C[7]);
            sC4[q][j][2] = make_float4(C[8], 0.f, 0.f, 0.f);
        }
    }
    __syncthreads();

    size_t regionStride = 3 * (size_t)B;
    if (t0 < nGroups) process_group(xa, t0, sC4, out, regionStride);
    if (t1 < nGroups) process_group(xb, t1, sC4, out, regionStride);
}

extern "C" void kernel_launch(void* const* d_in, const int* in_sizes, int n_in,
                              void* d_out, int out_size) {
    const float* x  = (const float*)d_in[0];
    const float* wp = (const float*)d_in[1];
    const float* wm = (const float*)d_in[2];
    const float* ws = (const float*)d_in[3];
    float* out = (float*)d_out;
    int B = in_sizes[0];

    int nGroups = B >> 2;                       // 262144 @ B=2^20
    int threads = 256;
    int blocks = (nGroups / 2 + threads - 1) / threads;   // 512: 2 groups/thread
    qmdn_fused<<<blocks, threads>>>((const float4*)x, wp, wm, ws, out, B);
}

// round 12
// speedup vs baseline: 1.0329x; 1.0329x over previous
#include <cuda_runtime.h>
#include <cstdint>

#define LAYERS 8
#define EPS_F 1e-7f

// Quadratic-form coefficients: p_j(x) = (1,u0,v0) C^j (1,u1,v1)^T,
// u0=cos x, v0=sin x, u1=cos(pi x/2), v1=sin(pi x/2).
// C rows padded to 12 floats (3 x float4).
__device__ float4 g_C4[3][4][3];

// ---------------------------------------------------------------------------
// Pre-kernel: 1 block, 3 warps (one per circuit), cooperative build of C^j.
// ---------------------------------------------------------------------------
__global__ void qmdn_pre(const float* __restrict__ wp,
                         const float* __restrict__ wm,
                         const float* __restrict__ ws) {
    __shared__ float sR[3][LAYERS][2][2][2][2];
    __shared__ float sP[3][LAYERS][4][4][2];
    __shared__ float sM[3][4][4][2];

    int wid  = threadIdx.x >> 5;
    int lane = threadIdx.x & 31;
    if (wid >= 3) return;
    int q = wid;
    const float* w = (q == 0) ? wp : (q == 1) ? wm : ws;

    if (lane < 16) {   // 16 Rot gates in parallel (lane = 2*layer + wire)
        int l = lane >> 1, wi = lane & 1;
        float phi = w[(l * 2 + wi) * 3 + 0];
        float th  = w[(l * 2 + wi) * 3 + 1];
        float om  = w[(l * 2 + wi) * 3 + 2];
        float st, ct, sapo, capo, samo, camo;
        __sincosf(0.5f * th, &st, &ct);
        __sincosf(0.5f * (phi + om), &sapo, &capo);
        __sincosf(0.5f * (phi - om), &samo, &camo);
        sR[q][l][wi][0][0][0] =  capo * ct;  sR[q][l][wi][0][0][1] = -sapo * ct;
        sR[q][l][wi][0][1][0] = -camo * st;  sR[q][l][wi][0][1][1] = -samo * st;
        sR[q][l][wi][1][0][0] =  camo * st;  sR[q][l][wi][1][0][1] = -samo * st;
        sR[q][l][wi][1][1][0] =  capo * ct;  sR[q][l][wi][1][1][1] =  sapo * ct;
    }
    __syncwarp();

    if (lane < 16) {   // per-layer row-permuted Kronecker
        int r = lane >> 2, c = lane & 3;
        const int src[4] = {0, 2, 3, 1};
        int rs = src[r], i0 = rs >> 1, j0 = rs & 1, i1 = c >> 1, j1 = c & 1;
#pragma unroll
        for (int l = 0; l < LAYERS; l++) {
            float ar = sR[q][l][0][i0][i1][0], ai = sR[q][l][0][i0][i1][1];
            float br = sR[q][l][1][j0][j1][0], bi = sR[q][l][1][j0][j1][1];
            sP[q][l][r][c][0] = ar * br - ai * bi;
            sP[q][l][r][c][1] = ar * bi + ai * br;
        }
    }
    __syncwarp();

    for (int np = 4; np >= 1; np >>= 1) {   // log-tree product U = PK7..PK0
        float res[4][2];
        if (lane < 16) {
            int r = lane >> 2, c = lane & 3;
            for (int m = 0; m < np; m++) {
                float sr = 0.f, si = 0.f;
#pragma unroll
                for (int k = 0; k < 4; k++) {
                    float ar = sP[q][2 * m + 1][r][k][0], ai = sP[q][2 * m + 1][r][k][1];
                    float br = sP[q][2 * m][k][c][0],     bi = sP[q][2 * m][k][c][1];
                    sr += ar * br - ai * bi;
                    si += ar * bi + ai * br;
                }
                res[m][0] = sr; res[m][1] = si;
            }
        }
        __syncwarp();
        if (lane < 16) {
            int r = lane >> 2, c = lane & 3;
            for (int m = 0; m < np; m++) {
                sP[q][m][r][c][0] = res[m][0];
                sP[q][m][r][c][1] = res[m][1];
            }
        }
        __syncwarp();
    }

    if (lane < 16) {   // fold column phases {1,-i,-i,-1}
        int r = lane >> 2, c = lane & 3;
        float ur = sP[q][0][r][c][0], ui = sP[q][0][r][c][1];
        float mr, mi;
        if (c == 0)      { mr =  ur; mi =  ui; }
        else if (c == 3) { mr = -ur; mi = -ui; }
        else             { mr =  ui; mi = -ur; }   // -i*(a+bi) = b - ai
        sM[q][r][c][0] = mr;
        sM[q][r][c][1] = mi;
    }
    __syncwarp();

    if (lane < 4) {    // build padded C^j, write to global
        int j = lane;
        float mr[4], mi[4];
#pragma unroll
        for (int k = 0; k < 4; k++) { mr[k] = sM[q][j][k][0]; mi[k] = sM[q][j][k][1]; }
        const float bas[3][3] = { {0.5f,  0.5f, 0.f},
                                  {0.f,   0.f,  0.5f},
                                  {0.5f, -0.5f, 0.f} };
        float C[9] = {0,0,0,0,0,0,0,0,0};
#pragma unroll
        for (int k = 0; k < 4; k++)
#pragma unroll
            for (int l = 0; l < 4; l++) {
                float Q = mr[k] * mr[l] + mi[k] * mi[l];   // Re(z_k conj(z_l))
                int a0 = (k >> 1) + (l >> 1);
                int b1 = (k & 1) + (l & 1);
#pragma unroll
                for (int al = 0; al < 3; al++)
#pragma unroll
                    for (int be = 0; be < 3; be++)
                        C[al * 3 + be] += Q * bas[a0][al] * bas[b1][be];
            }
        g_C4[q][j][0] = make_float4(C[0], C[1], C[2], C[3]);
        g_C4[q][j][1] = make_float4(C[4], C[5], C[6], C[7]);
        g_C4[q][j][2] = make_float4(C[8], 0.f, 0.f, 0.f);
    }
}

// ---------------------------------------------------------------------------
// Main kernel: no smem, no barrier. 4 elems/thread, rows-outer, C via __ldg
// (broadcast L1-resident). out: [pi (B,3) | mu (B,3) | sigma (B,3)] row-major.
// ---------------------------------------------------------------------------
__global__ void __launch_bounds__(256, 4)
qmdn_main(const float4* __restrict__ x4, float* __restrict__ out, int B) {
    int nGroups = B >> 2;
    int t = blockIdx.x * blockDim.x + threadIdx.x;
    if (t >= nGroups) return;

    const float CLIP_LO = EPS_F;
    const float CLIP_HI = 1.0f - EPS_F;
    const float LN2 = 0.69314718056f;
    size_t regionStride = 3 * (size_t)B;

    float4 xv = x4[t];
    float xs[4] = {xv.x, xv.y, xv.z, xv.w};
    float u0[4], v0[4], u1[4], v1[4];
#pragma unroll
    for (int e = 0; e < 4; e++) {
        __sincosf(xs[e], &v0[e], &u0[e]);
        __sincosf(1.5707963267948966f * xs[e], &v1[e], &u1[e]);
    }

#pragma unroll
    for (int q = 0; q < 3; q++) {
        int nrows = (q == 0) ? 3 : 4;
        float p[4][4];   // [row][elem]
#pragma unroll
        for (int j = 0; j < 4; j++) {
            if (j >= nrows) break;
            float4 c0 = __ldg(&g_C4[q][j][0]);   // C0 C1 C2 C3
            float4 c1 = __ldg(&g_C4[q][j][1]);   // C4 C5 C6 C7
            float4 c2 = __ldg(&g_C4[q][j][2]);   // C8 - - -
#pragma unroll
            for (int e = 0; e < 4; e++) {
                float w0 = fmaf(v1[e], c0.z, fmaf(u1[e], c0.y, c0.x));
                float w1 = fmaf(v1[e], c1.y, fmaf(u1[e], c1.x, c0.w));
                float w2 = fmaf(v1[e], c2.x, fmaf(u1[e], c1.w, c1.z));
                p[j][e] = fmaf(v0[e], w2, fmaf(u0[e], w1, w0));
            }
        }

        float o[12];
#pragma unroll
        for (int e = 0; e < 4; e++) {
            if (q == 0) {
                float inv = __fdividef(1.0f, p[0][e] + p[1][e] + p[2][e]);
                o[e * 3 + 0] = p[0][e] * inv;
                o[e * 3 + 1] = p[1][e] * inv;
                o[e * 3 + 2] = p[2][e] * inv;
            } else {
                float pc[4];
#pragma unroll
                for (int j = 0; j < 4; j++)
                    pc[j] = fminf(fmaxf(p[j][e], CLIP_LO), CLIP_HI);
                if (q == 1) {
                    float l3 = __log2f(pc[3]);
                    o[e * 3 + 0] = (__log2f(pc[0]) - l3) * LN2;
                    o[e * 3 + 1] = (__log2f(pc[1]) - l3) * LN2;
                    o[e * 3 + 2] = (__log2f(pc[2]) - l3) * LN2;
                } else {
                    float inv = __fdividef(1.0f, pc[3]);
                    o[e * 3 + 0] = pc[0] * inv;
                    o[e * 3 + 1] = pc[1] * inv;
                    o[e * 3 + 2] = pc[2] * inv;
                }
            }
        }
        float4* dst = (float4*)(out + q * regionStride + (size_t)t * 12);
        dst[0] = make_float4(o[0], o[1], o[2],  o[3]);
        dst[1] = make_float4(o[4], o[5], o[6],  o[7]);
        dst[2] = make_float4(o[8], o[9], o[10], o[11]);
    }
}

extern "C" void kernel_launch(void* const* d_in, const int* in_sizes, int n_in,
                              void* d_out, int out_size) {
    const float* x  = (const float*)d_in[0];
    const float* wp = (const float*)d_in[1];
    const float* wm = (const float*)d_in[2];
    const float* ws = (const float*)d_in[3];
    float* out = (float*)d_out;
    int B = in_sizes[0];

    qmdn_pre<<<1, 96>>>(wp, wm, ws);

    int nGroups = B >> 2;
    int threads = 256;
    int blocks = (nGroups + threads - 1) / threads;   // 1024 @ B=2^20
    qmdn_main<<<blocks, threads>>>((const float4*)x, out, B);
}